// round 6
// baseline (speedup 1.0000x reference)
#include <cuda_runtime.h>
#include <stdint.h>

// GCN layer, atomic-free aggregation via counting-sort by dst.
// NOTE: src/dst are INT32 (JAX default x64-disabled downcasts the reference's
// "int64" randint to int32) — reading them as int64 was the source of the
// cudaErrorInvalidAddressSpace traps in earlier rounds.
//
// out = relu( (indeg>0 ? (sum_{e: dst=n} feat[src_e]*ci[src_e]) * cj[n]
//                      : feat[n]) @ W^T + b )

#define N_NODES 50000
#define N_EDGES 1600000
#define D       48
#define DV      12           // float4 chunks per row
#define SCAN_T  1024

// Scratch (__device__ globals; no allocation allowed)
__device__ float4 g_agg[N_NODES * DV];       // 9.6 MB  aggregated messages
__device__ float4 g_featci[N_NODES * DV];    // 9.6 MB  feat * ci (premultiplied)
__device__ int    g_outdeg[N_NODES];
__device__ int    g_indeg[N_NODES];
__device__ int    g_off[N_NODES];            // exclusive prefix of indeg
__device__ int    g_cursor[N_NODES];         // bucket fill cursors
__device__ int    g_sorted_src[N_EDGES];     // src ids grouped by dst (6.4 MB)

__device__ __forceinline__ int clamp_node(int v) {
    // trap insurance: keep every index inside the node range
    return ((unsigned)v < (unsigned)N_NODES) ? v : 0;
}

// ---------------------------------------------------------------------------
__global__ void zero_kernel() {
    int i = blockIdx.x * blockDim.x + threadIdx.x;
    if (i < N_NODES) { g_outdeg[i] = 0; g_indeg[i] = 0; }
}

// ---------------------------------------------------------------------------
__global__ void degree_kernel(const int* __restrict__ src,
                              const int* __restrict__ dst) {
    int e = blockIdx.x * blockDim.x + threadIdx.x;
    if (e >= N_EDGES) return;
    atomicAdd(&g_outdeg[clamp_node(src[e])], 1);   // int RED, spread addresses
    atomicAdd(&g_indeg[clamp_node(dst[e])], 1);
}

// ---------------------------------------------------------------------------
// featci[n] = feat[n] * rsqrt(max(outdeg[n],1)), 12 threads per node
__global__ void premul_kernel(const float4* __restrict__ feat4) {
    unsigned idx = blockIdx.x * blockDim.x + threadIdx.x;
    if (idx >= (unsigned)N_NODES * DV) return;
    unsigned n = idx / DV;
    float ci = rsqrtf(fmaxf((float)g_outdeg[n], 1.0f));
    float4 v = feat4[idx];
    v.x *= ci; v.y *= ci; v.z *= ci; v.w *= ci;
    g_featci[idx] = v;
}

// ---------------------------------------------------------------------------
// Single-block exclusive scan of g_indeg -> g_off (and g_cursor).
__global__ void scan_kernel() {
    __shared__ int ssum[SCAN_T];
    int t = threadIdx.x;
    const int per = (N_NODES + SCAN_T - 1) / SCAN_T;   // 49
    int start = t * per;
    int end   = start + per; if (end > N_NODES) end = N_NODES;

    int s = 0;
    for (int i = start; i < end; i++) s += g_indeg[i];
    ssum[t] = s;
    __syncthreads();

    // Hillis-Steele inclusive scan over the 1024 partials
    for (int off = 1; off < SCAN_T; off <<= 1) {
        int v = (t >= off) ? ssum[t - off] : 0;
        __syncthreads();
        ssum[t] += v;
        __syncthreads();
    }
    int run = (t == 0) ? 0 : ssum[t - 1];   // exclusive base for this chunk

    for (int i = start; i < end; i++) {
        g_off[i]    = run;
        g_cursor[i] = run;
        run += g_indeg[i];
    }
}

// ---------------------------------------------------------------------------
// Bucket edges by dst: sorted_src[pos] = src
__global__ void bucket_kernel(const int* __restrict__ src,
                              const int* __restrict__ dst) {
    int e = blockIdx.x * blockDim.x + threadIdx.x;
    if (e >= N_EDGES) return;
    int d = clamp_node(dst[e]);
    int pos = atomicAdd(&g_cursor[d], 1);
    if ((unsigned)pos < (unsigned)N_EDGES)
        g_sorted_src[pos] = clamp_node(src[e]);
}

// ---------------------------------------------------------------------------
// Atomic-free gather: 12 threads per node, thread owns one float4 column.
// featci is premultiplied by ci, so the inner loop is a pure float4 sum.
__global__ void gather_kernel() {
    unsigned idx = blockIdx.x * blockDim.x + threadIdx.x;
    if (idx >= (unsigned)N_NODES * DV) return;
    unsigned n = idx / DV;
    unsigned c = idx - n * DV;

    int beg = g_off[n];
    int cnt = g_indeg[n];

    float4 acc = make_float4(0.f, 0.f, 0.f, 0.f);
    int k = 0;
    for (; k + 2 <= cnt; k += 2) {
        int s0 = g_sorted_src[beg + k];
        int s1 = g_sorted_src[beg + k + 1];
        float4 v0 = g_featci[(unsigned)s0 * DV + c];
        float4 v1 = g_featci[(unsigned)s1 * DV + c];
        acc.x += v0.x; acc.y += v0.y; acc.z += v0.z; acc.w += v0.w;
        acc.x += v1.x; acc.y += v1.y; acc.z += v1.z; acc.w += v1.w;
    }
    if (k < cnt) {
        int s0 = g_sorted_src[beg + k];
        float4 v0 = g_featci[(unsigned)s0 * DV + c];
        acc.x += v0.x; acc.y += v0.y; acc.z += v0.z; acc.w += v0.w;
    }
    g_agg[idx] = acc;
}

// ---------------------------------------------------------------------------
// h = indeg>0 ? agg*cj : feat ; out = relu(h @ W^T + b)
__global__ void finalize_kernel(const float* __restrict__ feat,
                                const float* __restrict__ W,
                                const float* __restrict__ b,
                                float* __restrict__ out) {
    __shared__ float Ws[D * D];
    __shared__ float bs[D];
    for (int i = threadIdx.x; i < D * D; i += blockDim.x) Ws[i] = W[i];
    if (threadIdx.x < D) bs[threadIdx.x] = b[threadIdx.x];
    __syncthreads();

    int n = blockIdx.x * blockDim.x + threadIdx.x;
    if (n >= N_NODES) return;

    int indeg = g_indeg[n];
    float cj = rsqrtf(fmaxf((float)indeg, 1.0f));
    const float* aggp = (const float*)g_agg;
    const float* hp   = (indeg > 0) ? (aggp + (size_t)n * D) : (feat + (size_t)n * D);
    float scale       = (indeg > 0) ? cj : 1.0f;

    float acc[D];
#pragma unroll
    for (int o = 0; o < D; o++) acc[o] = bs[o];

#pragma unroll 4
    for (int i = 0; i < D; i++) {
        float hi = hp[i] * scale;
#pragma unroll
        for (int o = 0; o < D; o++) acc[o] += hi * Ws[o * D + i];
    }

    float4* out4 = (float4*)(out + (size_t)n * D);
#pragma unroll
    for (int k = 0; k < DV; k++) {
        float4 v;
        v.x = fmaxf(acc[4 * k + 0], 0.f);
        v.y = fmaxf(acc[4 * k + 1], 0.f);
        v.z = fmaxf(acc[4 * k + 2], 0.f);
        v.w = fmaxf(acc[4 * k + 3], 0.f);
        out4[k] = v;
    }
}

// ---------------------------------------------------------------------------
extern "C" void kernel_launch(void* const* d_in, const int* in_sizes, int n_in,
                              void* d_out, int out_size) {
    const float* feat = (const float*)d_in[0];
    const int*   src  = (const int*)d_in[1];    // int32 (JAX x64 disabled)
    const int*   dst  = (const int*)d_in[2];
    const float* W    = (const float*)d_in[3];
    const float* b    = (const float*)d_in[4];
    float*       out  = (float*)d_out;
    (void)in_sizes; (void)n_in; (void)out_size;

    const int TB = 256;

    zero_kernel<<<(N_NODES + TB - 1) / TB, TB>>>();
    degree_kernel<<<(N_EDGES + TB - 1) / TB, TB>>>(src, dst);
    {
        unsigned total = (unsigned)N_NODES * DV;   // 600000
        premul_kernel<<<(total + TB - 1) / TB, TB>>>((const float4*)feat);
    }
    scan_kernel<<<1, SCAN_T>>>();
    bucket_kernel<<<(N_EDGES + TB - 1) / TB, TB>>>(src, dst);
    {
        unsigned total = (unsigned)N_NODES * DV;   // 600000
        gather_kernel<<<(total + 191) / 192, 192>>>();
    }
    finalize_kernel<<<(N_NODES + TB - 1) / TB, TB>>>(feat, W, b, out);
}

// round 7
// speedup vs baseline: 1.6914x; 1.6914x over previous
#include <cuda_runtime.h>
#include <stdint.h>

// GCN layer, atomic-free aggregation via counting-sort by dst.
// src/dst are INT32 (JAX with x64 disabled).
//
// out = relu( (indeg>0 ? (sum_{e: dst=n} feat[src_e]*ci[src_e]) * cj[n]
//                      : feat[n]) @ W^T + b )

#define N_NODES   50000
#define N_EDGES   1600000
#define D         48
#define DV        12            // float4 chunks per row
#define SCAN_B    256           // scan block size
#define SCAN_G    ((N_NODES + SCAN_B - 1) / SCAN_B)   // 196 blocks

// Scratch (__device__ globals; no allocation allowed)
__device__ float4 g_agg[N_NODES * DV];       // 9.6 MB  aggregated messages
__device__ float4 g_featci[N_NODES * DV];    // 9.6 MB  feat * ci (premultiplied)
__device__ int    g_outdeg[N_NODES];
__device__ int    g_indeg[N_NODES];
__device__ int    g_off[N_NODES];            // exclusive prefix of indeg
__device__ int    g_cursor[N_NODES];         // bucket fill cursors
__device__ int    g_sorted_src[N_EDGES];     // src ids grouped by dst (6.4 MB)
__device__ int    g_blocksum[SCAN_G];        // per-block sums
__device__ int    g_blockbase[SCAN_G];       // exclusive scan of block sums

__device__ __forceinline__ int clamp_node(int v) {
    return ((unsigned)v < (unsigned)N_NODES) ? v : 0;
}

// ---------------------------------------------------------------------------
__global__ void zero_kernel() {
    int i = blockIdx.x * blockDim.x + threadIdx.x;
    if (i < N_NODES) { g_outdeg[i] = 0; g_indeg[i] = 0; }
}

// ---------------------------------------------------------------------------
__global__ void degree_kernel(const int* __restrict__ src,
                              const int* __restrict__ dst) {
    int e = blockIdx.x * blockDim.x + threadIdx.x;
    if (e >= N_EDGES) return;
    atomicAdd(&g_outdeg[clamp_node(src[e])], 1);
    atomicAdd(&g_indeg[clamp_node(dst[e])], 1);
}

// ---------------------------------------------------------------------------
// featci[n] = feat[n] * rsqrt(max(outdeg[n],1)), 12 threads per node
__global__ void premul_kernel(const float4* __restrict__ feat4) {
    unsigned idx = blockIdx.x * blockDim.x + threadIdx.x;
    if (idx >= (unsigned)N_NODES * DV) return;
    unsigned n = idx / DV;
    float ci = rsqrtf(fmaxf((float)g_outdeg[n], 1.0f));
    float4 v = feat4[idx];
    v.x *= ci; v.y *= ci; v.z *= ci; v.w *= ci;
    g_featci[idx] = v;
}

// ---------------------------------------------------------------------------
// Scan phase A: per-block sum of indeg chunk
__global__ void scanA_kernel() {
    __shared__ int sh[SCAN_B];
    int i = blockIdx.x * SCAN_B + threadIdx.x;
    int v = (i < N_NODES) ? g_indeg[i] : 0;
    sh[threadIdx.x] = v;
    __syncthreads();
    for (int off = SCAN_B / 2; off > 0; off >>= 1) {
        if (threadIdx.x < off) sh[threadIdx.x] += sh[threadIdx.x + off];
        __syncthreads();
    }
    if (threadIdx.x == 0) g_blocksum[blockIdx.x] = sh[0];
}

// Scan phase B: one block exclusive-scans the 196 block sums
__global__ void scanB_kernel() {
    __shared__ int sh[SCAN_G];
    int t = threadIdx.x;
    if (t < SCAN_G) sh[t] = g_blocksum[t];
    __syncthreads();
    // Hillis-Steele inclusive scan (256 threads cover 196 entries)
    for (int off = 1; off < SCAN_G; off <<= 1) {
        int v = (t >= off && t < SCAN_G) ? sh[t - off] : 0;
        __syncthreads();
        if (t < SCAN_G) sh[t] += v;
        __syncthreads();
    }
    if (t < SCAN_G) g_blockbase[t] = (t == 0) ? 0 : sh[t - 1];
}

// Scan phase C: intra-block exclusive scan + base -> g_off, g_cursor
__global__ void scanC_kernel() {
    __shared__ int sh[SCAN_B];
    int i = blockIdx.x * SCAN_B + threadIdx.x;
    int t = threadIdx.x;
    int v = (i < N_NODES) ? g_indeg[i] : 0;
    sh[t] = v;
    __syncthreads();
    // Hillis-Steele inclusive scan
    for (int off = 1; off < SCAN_B; off <<= 1) {
        int u = (t >= off) ? sh[t - off] : 0;
        __syncthreads();
        sh[t] += u;
        __syncthreads();
    }
    if (i < N_NODES) {
        int excl = g_blockbase[blockIdx.x] + sh[t] - v;   // exclusive = incl - self
        g_off[i]    = excl;
        g_cursor[i] = excl;
    }
}

// ---------------------------------------------------------------------------
// Bucket edges by dst: sorted_src[pos] = src
__global__ void bucket_kernel(const int* __restrict__ src,
                              const int* __restrict__ dst) {
    int e = blockIdx.x * blockDim.x + threadIdx.x;
    if (e >= N_EDGES) return;
    int d = clamp_node(dst[e]);
    int pos = atomicAdd(&g_cursor[d], 1);
    if ((unsigned)pos < (unsigned)N_EDGES)
        g_sorted_src[pos] = clamp_node(src[e]);
}

// ---------------------------------------------------------------------------
// Atomic-free gather: 12 threads per node, thread owns one float4 column.
__global__ void gather_kernel() {
    unsigned idx = blockIdx.x * blockDim.x + threadIdx.x;
    if (idx >= (unsigned)N_NODES * DV) return;
    unsigned n = idx / DV;
    unsigned c = idx - n * DV;

    int beg = g_off[n];
    int cnt = g_indeg[n];

    float4 acc = make_float4(0.f, 0.f, 0.f, 0.f);
    int k = 0;
    for (; k + 2 <= cnt; k += 2) {
        int s0 = g_sorted_src[beg + k];
        int s1 = g_sorted_src[beg + k + 1];
        float4 v0 = g_featci[(unsigned)s0 * DV + c];
        float4 v1 = g_featci[(unsigned)s1 * DV + c];
        acc.x += v0.x; acc.y += v0.y; acc.z += v0.z; acc.w += v0.w;
        acc.x += v1.x; acc.y += v1.y; acc.z += v1.z; acc.w += v1.w;
    }
    if (k < cnt) {
        int s0 = g_sorted_src[beg + k];
        float4 v0 = g_featci[(unsigned)s0 * DV + c];
        acc.x += v0.x; acc.y += v0.y; acc.z += v0.z; acc.w += v0.w;
    }
    g_agg[idx] = acc;
}

// ---------------------------------------------------------------------------
// h = indeg>0 ? agg*cj : feat ; out = relu(h @ W^T + b)
__global__ void finalize_kernel(const float* __restrict__ feat,
                                const float* __restrict__ W,
                                const float* __restrict__ b,
                                float* __restrict__ out) {
    __shared__ float Ws[D * D];
    __shared__ float bs[D];
    for (int i = threadIdx.x; i < D * D; i += blockDim.x) Ws[i] = W[i];
    if (threadIdx.x < D) bs[threadIdx.x] = b[threadIdx.x];
    __syncthreads();

    int n = blockIdx.x * blockDim.x + threadIdx.x;
    if (n >= N_NODES) return;

    int indeg = g_indeg[n];
    float cj = rsqrtf(fmaxf((float)indeg, 1.0f));
    const float* aggp = (const float*)g_agg;
    const float* hp   = (indeg > 0) ? (aggp + (size_t)n * D) : (feat + (size_t)n * D);
    float scale       = (indeg > 0) ? cj : 1.0f;

    float acc[D];
#pragma unroll
    for (int o = 0; o < D; o++) acc[o] = bs[o];

#pragma unroll 4
    for (int i = 0; i < D; i++) {
        float hi = hp[i] * scale;
#pragma unroll
        for (int o = 0; o < D; o++) acc[o] += hi * Ws[o * D + i];
    }

    float4* out4 = (float4*)(out + (size_t)n * D);
#pragma unroll
    for (int k = 0; k < DV; k++) {
        float4 v;
        v.x = fmaxf(acc[4 * k + 0], 0.f);
        v.y = fmaxf(acc[4 * k + 1], 0.f);
        v.z = fmaxf(acc[4 * k + 2], 0.f);
        v.w = fmaxf(acc[4 * k + 3], 0.f);
        out4[k] = v;
    }
}

// ---------------------------------------------------------------------------
extern "C" void kernel_launch(void* const* d_in, const int* in_sizes, int n_in,
                              void* d_out, int out_size) {
    const float* feat = (const float*)d_in[0];
    const int*   src  = (const int*)d_in[1];    // int32
    const int*   dst  = (const int*)d_in[2];
    const float* W    = (const float*)d_in[3];
    const float* b    = (const float*)d_in[4];
    float*       out  = (float*)d_out;
    (void)in_sizes; (void)n_in; (void)out_size;

    const int TB = 256;

    zero_kernel<<<(N_NODES + TB - 1) / TB, TB>>>();
    degree_kernel<<<(N_EDGES + TB - 1) / TB, TB>>>(src, dst);
    {
        unsigned total = (unsigned)N_NODES * DV;   // 600000
        premul_kernel<<<(total + TB - 1) / TB, TB>>>((const float4*)feat);
    }
    scanA_kernel<<<SCAN_G, SCAN_B>>>();
    scanB_kernel<<<1, SCAN_B>>>();
    scanC_kernel<<<SCAN_G, SCAN_B>>>();
    bucket_kernel<<<(N_EDGES + TB - 1) / TB, TB>>>(src, dst);
    {
        unsigned total = (unsigned)N_NODES * DV;   // 600000
        gather_kernel<<<(total + 191) / 192, 192>>>();
    }
    finalize_kernel<<<(N_NODES + TB - 1) / TB, TB>>>(feat, W, b, out);
}